// round 14
// baseline (speedup 1.0000x reference)
#include <cuda_runtime.h>
#include <cuda_fp16.h>
#include <math.h>
#include <stdint.h>

#define B_     256
#define NG_    64
#define HEADS  6
#define CH     192
#define NTOK   216
#define HD     32
#define M_POS  1331
#define PDIM   12
#define MROWS  (B_*NTOK)   // 55296

// fp16 attention tiling
#define NKP     224        // keys padded to 14*16
#define KS_STRH 40         // K smem row stride in halves: conflict-free frag loads
#define VT_STRH 248        // V^T smem row stride in halves: conflict-free frag loads
#define KT16    14         // 16-key tiles

// fp16 GEMM (A-resident, whole-W-block) tiling
#define AHS     200        // SMEM row stride in halves (banks 4*grp+tig, conflict-free)
#define GSMEM   ((128*AHS + 64*AHS)*2)   // 76800 B

// ---------------- scratch (all intermediates fp16) ----------------
__device__ __half   g_qh   [(size_t)MROWS*CH];
__device__ __half   g_kvh  [(size_t)MROWS*2*CH];
__device__ __half   g_atth [(size_t)MROWS*CH];
__device__ __half   g_wh   [(size_t)4*CH*CH];     // [Wqkv(3C) ; Wproj(C)] rows, half
__device__ float    g_pos  [HEADS*M_POS];
__device__ uint32_t g_mbits[(size_t)NG_*NTOK*8];  // mask bitmask: 1 = masked

__device__ __forceinline__ uint32_t pack_h2(float a, float b) {
    __half2 h = __floats2half2_rn(a, b);
    return *(uint32_t*)&h;
}

// ---------------- tiny dynamic position-bias MLP ----------------
__device__ __forceinline__ void ln12(float* t, const float* g, const float* b) {
    float mu = 0.f;
    #pragma unroll
    for (int i = 0; i < PDIM; i++) mu += t[i];
    mu *= (1.f/PDIM);
    float v = 0.f;
    #pragma unroll
    for (int i = 0; i < PDIM; i++) { float d = t[i]-mu; v += d*d; }
    v *= (1.f/PDIM);
    float inv = rsqrtf(v + 1e-5f);
    #pragma unroll
    for (int i = 0; i < PDIM; i++) t[i] = (t[i]-mu)*inv*g[i] + b[i];
}

__global__ void pos_mlp_kernel(
    const float* __restrict__ ppw, const float* __restrict__ ppb,
    const float* __restrict__ g1,  const float* __restrict__ be1,
    const float* __restrict__ w1,  const float* __restrict__ b1,
    const float* __restrict__ g2,  const float* __restrict__ be2,
    const float* __restrict__ w2,  const float* __restrict__ b2,
    const float* __restrict__ g3,  const float* __restrict__ be3,
    const float* __restrict__ w3,  const float* __restrict__ b3)
{
    int m = blockIdx.x*blockDim.x + threadIdx.x;
    if (m >= M_POS) return;
    float c0 = (float)(m/121 - 5);
    float c1 = (float)((m/11)%11 - 5);
    float c2 = (float)(m%11 - 5);
    float t[PDIM], u[PDIM];
    #pragma unroll
    for (int i = 0; i < PDIM; i++)
        t[i] = ppw[i*3+0]*c0 + ppw[i*3+1]*c1 + ppw[i*3+2]*c2 + ppb[i];
    ln12(t, g1, be1);
    #pragma unroll
    for (int i = 0; i < PDIM; i++) {
        float acc = b1[i];
        #pragma unroll
        for (int j = 0; j < PDIM; j++) acc += w1[i*PDIM+j]*fmaxf(t[j],0.f);
        u[i] = acc;
    }
    ln12(u, g2, be2);
    #pragma unroll
    for (int i = 0; i < PDIM; i++) {
        float acc = b2[i];
        #pragma unroll
        for (int j = 0; j < PDIM; j++) acc += w2[i*PDIM+j]*fmaxf(u[j],0.f);
        t[i] = acc;
    }
    ln12(t, g3, be3);
    #pragma unroll
    for (int h = 0; h < HEADS; h++) {
        float acc = b3[h];
        #pragma unroll
        for (int j = 0; j < PDIM; j++) acc += w3[h*PDIM+j]*fmaxf(t[j],0.f);
        g_pos[h*M_POS + m] = acc;
    }
}

// ---------------- one-shot weight conversion fp32 -> fp16 ----------------
__global__ void conv_w_kernel(const float* __restrict__ Wqkv,
                              const float* __restrict__ Wproj)
{
    int i = (blockIdx.x*256 + threadIdx.x) * 4;
    const int QKV = 3*CH*CH;
    const int TOT = 4*CH*CH;
    if (i >= TOT) return;
    float4 v = (i < QKV) ? *(const float4*)(Wqkv + i)
                         : *(const float4*)(Wproj + (i - QKV));
    uint2 p = make_uint2(pack_h2(v.x, v.y), pack_h2(v.z, v.w));
    *(uint2*)&g_wh[i] = p;
}

// ---------------- one-shot mask -> bitmask ----------------
__global__ void mask_bits_kernel(const float* __restrict__ mask)
{
    int row  = (blockIdx.x*256 + threadIdx.x) >> 5;   // g*NTOK + n
    int lane = threadIdx.x & 31;
    if (row >= NG_*NTOK) return;
    const float* r = mask + (size_t)row*NTOK;
    #pragma unroll
    for (int i = 0; i < 7; i++) {
        int m = i*32 + lane;
        bool bit = (m < NTOK) && (r[m] < -1.f);
        uint32_t wv = __ballot_sync(0xffffffffu, bit);
        if (lane == 0) g_mbits[(size_t)row*8 + i] = wv;
    }
}

// ---------------- FP16 tensor-core GEMM: A-resident, whole-W-block, reg prefetch ----------------
template<bool A_HALF, bool OUT_HALF>
__global__ __launch_bounds__(256)
void gemm_f16_big(const void* __restrict__ Ain, const __half* __restrict__ Wh,
                  const float* __restrict__ bias, void* __restrict__ Cout, int Ndim)
{
    extern __shared__ __half sg[];
    __half* Ah = sg;                 // [128][AHS]
    __half* Ws = Ah + 128*AHS;       // [64][AHS]

    int tid  = threadIdx.x;
    int w    = tid >> 5, lane = tid & 31;
    int grp  = lane >> 2, tig = lane & 3;
    int wm   = (w >> 1) * 32;
    int wn   = (w & 1) * 32;
    int m0   = blockIdx.x * 128;

    if (A_HALF) {
        const __half* Af = (const __half*)Ain + (size_t)m0*CH;
        #pragma unroll
        for (int i = 0; i < 24; i++) {
            int idx = i*256 + tid;
            int row = idx/48, c4 = idx%48;
            uint2 v = *(const uint2*)(Af + (size_t)row*CH + c4*4);
            *(uint2*)&Ah[row*AHS + c4*4] = v;
        }
    } else {
        const float* Af = (const float*)Ain + (size_t)m0*CH;
        #pragma unroll
        for (int i = 0; i < 24; i++) {
            int idx = i*256 + tid;
            int row = idx/48, c4 = idx%48;
            float4 v = *(const float4*)(Af + (size_t)row*CH + c4*4);
            uint2 p = make_uint2(pack_h2(v.x, v.y), pack_h2(v.z, v.w));
            *(uint2*)&Ah[row*AHS + c4*4] = p;
        }
    }

    const uint32_t* Ahw = (const uint32_t*)Ah;
    uint32_t* Wsw = (uint32_t*)Ws;
    int nbc = Ndim >> 6;

    uint4 wR[6];
    #pragma unroll
    for (int i = 0; i < 6; i++) {
        int idx = i*256 + tid;
        int row = idx/24, c8 = idx%24;
        wR[i] = *(const uint4*)(Wh + (size_t)row*CH + c8*8);
    }

    for (int nb = 0; nb < nbc; nb++) {
        #pragma unroll
        for (int i = 0; i < 6; i++) {
            int idx = i*256 + tid;
            int row = idx/24, c8 = idx%24;
            *(uint4*)&Ws[row*AHS + c8*8] = wR[i];
        }
        __syncthreads();

        if (nb + 1 < nbc) {
            const __half* Wb = Wh + (size_t)(nb+1)*64*CH;
            #pragma unroll
            for (int i = 0; i < 6; i++) {
                int idx = i*256 + tid;
                int row = idx/24, c8 = idx%24;
                wR[i] = *(const uint4*)(Wb + (size_t)row*CH + c8*8);
            }
        }

        float acc[2][4][4];
        #pragma unroll
        for (int i = 0; i < 2; i++)
            #pragma unroll
            for (int j = 0; j < 4; j++)
                #pragma unroll
                for (int c = 0; c < 4; c++) acc[i][j][c] = 0.f;

        #pragma unroll
        for (int st = 0; st < 12; st++) {
            int ko = st*8;
            uint32_t af[2][4], bf[4][2];
            #pragma unroll
            for (int mf = 0; mf < 2; mf++) {
                int r = wm + mf*16 + grp;
                af[mf][0] = Ahw[(r    )*(AHS/2) + ko + tig];
                af[mf][1] = Ahw[(r + 8)*(AHS/2) + ko + tig];
                af[mf][2] = Ahw[(r    )*(AHS/2) + ko + tig + 4];
                af[mf][3] = Ahw[(r + 8)*(AHS/2) + ko + tig + 4];
            }
            #pragma unroll
            for (int nf = 0; nf < 4; nf++) {
                int n = wn + nf*8 + grp;
                bf[nf][0] = Wsw[n*(AHS/2) + ko + tig];
                bf[nf][1] = Wsw[n*(AHS/2) + ko + tig + 4];
            }
            #pragma unroll
            for (int mf = 0; mf < 2; mf++)
                #pragma unroll
                for (int nf = 0; nf < 4; nf++) {
                    asm volatile(
                        "mma.sync.aligned.m16n8k16.row.col.f32.f16.f16.f32 "
                        "{%0,%1,%2,%3}, {%4,%5,%6,%7}, {%8,%9}, {%0,%1,%2,%3};"
                        : "+f"(acc[mf][nf][0]), "+f"(acc[mf][nf][1]),
                          "+f"(acc[mf][nf][2]), "+f"(acc[mf][nf][3])
                        : "r"(af[mf][0]), "r"(af[mf][1]), "r"(af[mf][2]), "r"(af[mf][3]),
                          "r"(bf[nf][0]), "r"(bf[nf][1]));
                }
        }

        int n0 = nb*64;
        #pragma unroll
        for (int mf = 0; mf < 2; mf++) {
            #pragma unroll
            for (int nf = 0; nf < 4; nf++) {
                int col = n0 + wn + nf*8 + 2*tig;
                float bx = bias[col], by = bias[col+1];
                int r0 = m0 + wm + mf*16 + grp;
                if (OUT_HALF) {
                    __half* Co = (__half*)Cout;
                    *(uint32_t*)&Co[(size_t)r0*Ndim + col] =
                        pack_h2(acc[mf][nf][0] + bx, acc[mf][nf][1] + by);
                    *(uint32_t*)&Co[(size_t)(r0+8)*Ndim + col] =
                        pack_h2(acc[mf][nf][2] + bx, acc[mf][nf][3] + by);
                } else {
                    float* Co = (float*)Cout;
                    *(float2*)&Co[(size_t)r0*Ndim + col] =
                        make_float2(acc[mf][nf][0] + bx, acc[mf][nf][1] + by);
                    *(float2*)&Co[(size_t)(r0+8)*Ndim + col] =
                        make_float2(acc[mf][nf][2] + bx, acc[mf][nf][3] + by);
                }
            }
        }
        __syncthreads();
    }
}

// ---------------- fp16 tensor-core fused attention: m32 per warp ----------------
// 224 threads = 7 warps; warp w owns rows [32w, 32w+32) (two m16 tiles sharing K/V frags).
__global__ __launch_bounds__(224, 3)
void attn_tc_kernel()
{
    extern __shared__ __half smh[];
    __half*   Ksh   = smh;                          // [224][40] half
    __half*   Vth   = Ksh + NKP*KS_STRH;            // [32][248] half (V^T)
    float2*   poshd = (float2*)(Vth + 32*VT_STRH);  // [1331] (pos[a], pos[a-1])
    uint32_t* mbs   = (uint32_t*)(poshd + M_POS);   // [216][9] mask bits (stride 9)
    short*    midv  = (short*)(mbs + 216*9);        // [216] pid3 LUT

    int bh = blockIdx.x;
    int b  = bh / HEADS, h = bh % HEADS;
    int g  = b & (NG_-1);
    int tid = threadIdx.x;
    int w = tid >> 5, lane = tid & 31;
    int grp = lane >> 2, tig = lane & 3;

    const __half* kvbh = g_kvh + (size_t)b*NTOK*(2*CH);
    for (int e = tid; e < NKP*16; e += 224) {
        int m = e >> 4, d = (e & 15)*2;
        uint32_t ku = 0u, vu = 0u;
        if (m < NTOK) {
            ku = *(const uint32_t*)&kvbh[(size_t)m*(2*CH) + h*32 + d];
            vu = *(const uint32_t*)&kvbh[(size_t)m*(2*CH) + CH + h*32 + d];
        }
        *(uint32_t*)&Ksh[m*KS_STRH + d] = ku;
        __half2 vh = *(__half2*)&vu;
        Vth[(d    )*VT_STRH + m] = vh.x;
        Vth[(d + 1)*VT_STRH + m] = vh.y;
    }
    for (int e = tid; e < M_POS; e += 224) {
        float cur = g_pos[h*M_POS + e];
        float prv = (e > 0) ? g_pos[h*M_POS + e - 1] : 0.f;
        poshd[e] = make_float2(cur, prv);
    }
    {
        const uint32_t* mg = g_mbits + (size_t)g*NTOK*8;
        for (int e = tid; e < NTOK*8; e += 224)
            mbs[(e >> 3)*9 + (e & 7)] = mg[e];
    }
    for (int e = tid; e < NTOK; e += 224)
        midv[e] = (short)((e/36)*121 + ((e/6)%6)*11 + (e%6));
    __syncthreads();

    const __half* qbh = g_qh + (size_t)b*NTOK*CH + h*32;
    __half* obh = g_atth + (size_t)b*NTOK*CH + h*32;
    const float scale = 0.17677669529663687f;  // 32^-0.5

    // rows owned by this warp: two m16 tiles
    int r0 = w*32 + grp;        // ms=0 lower  (<= 199)
    int r1 = r0 + 8;            // ms=0 upper  (<= 207)
    int r2 = r0 + 16;           // ms=1 lower  (<= 215)
    int r3 = r0 + 24;           // ms=1 upper  (216..223 for w=6 -> clamped/guarded)
    int rc[4] = { r0, r1, r2, min(r3, NTOK-1) };

    // Q A-frags for both tiles
    uint32_t aq[2][2][4];
    #pragma unroll
    for (int ms = 0; ms < 2; ms++) {
        const __half* qlo = qbh + (size_t)rc[2*ms]*CH;
        const __half* qhi = qbh + (size_t)rc[2*ms+1]*CH;
        #pragma unroll
        for (int c = 0; c < 2; c++) {
            aq[ms][c][0] = *(const uint32_t*)&qlo[c*16 + 2*tig];
            aq[ms][c][1] = *(const uint32_t*)&qhi[c*16 + 2*tig];
            aq[ms][c][2] = *(const uint32_t*)&qlo[c*16 + 2*tig + 8];
            aq[ms][c][3] = *(const uint32_t*)&qhi[c*16 + 2*tig + 8];
        }
    }
    int nid[4];
    #pragma unroll
    for (int i = 0; i < 4; i++) nid[i] = midv[rc[i]];

    float o[2][4][4];
    #pragma unroll
    for (int ms = 0; ms < 2; ms++)
        #pragma unroll
        for (int dt = 0; dt < 4; dt++)
            #pragma unroll
            for (int c = 0; c < 4; c++) o[ms][dt][c] = 0.f;
    float rsum[4] = {0.f, 0.f, 0.f, 0.f};

    #pragma unroll 2
    for (int kt = 0; kt < KT16; kt++) {
        // shared K frags for this kt
        uint32_t kb[2][2], kd[2][2];
        int key0 = kt*16 + grp;
        #pragma unroll
        for (int c = 0; c < 2; c++) {
            kb[c][0] = *(const uint32_t*)&Ksh[(key0    )*KS_STRH + c*16 + 2*tig];
            kb[c][1] = *(const uint32_t*)&Ksh[(key0    )*KS_STRH + c*16 + 2*tig + 8];
            kd[c][0] = *(const uint32_t*)&Ksh[(key0 + 8)*KS_STRH + c*16 + 2*tig];
            kd[c][1] = *(const uint32_t*)&Ksh[(key0 + 8)*KS_STRH + c*16 + 2*tig + 8];
        }

        // mask words, 4 rows (broadcast LDS, stride-9 conflict-free)
        int mw = kt >> 1, msh = (kt & 1)*16 + 2*tig;
        uint32_t mwv[4];
        #pragma unroll
        for (int i = 0; i < 4; i++) mwv[i] = mbs[rc[i]*9 + mw] >> msh;

        int m0 = kt*16 + 2*tig;
        int mid0 = midv[m0];

        uint32_t pa[2][4];
        #pragma unroll
        for (int ms = 0; ms < 2; ms++) {
            float s0[4] = {0.f,0.f,0.f,0.f};
            float s1[4] = {0.f,0.f,0.f,0.f};
            #pragma unroll
            for (int c = 0; c < 2; c++) {
                asm volatile(
                    "mma.sync.aligned.m16n8k16.row.col.f32.f16.f16.f32 "
                    "{%0,%1,%2,%3}, {%4,%5,%6,%7}, {%8,%9}, {%0,%1,%2,%3};"
                    : "+f"(s0[0]), "+f"(s0[1]), "+f"(s0[2]), "+f"(s0[3])
                    : "r"(aq[ms][c][0]), "r"(aq[ms][c][1]),
                      "r"(aq[ms][c][2]), "r"(aq[ms][c][3]),
                      "r"(kb[c][0]), "r"(kb[c][1]));
                asm volatile(
                    "mma.sync.aligned.m16n8k16.row.col.f32.f16.f16.f32 "
                    "{%0,%1,%2,%3}, {%4,%5,%6,%7}, {%8,%9}, {%0,%1,%2,%3};"
                    : "+f"(s1[0]), "+f"(s1[1]), "+f"(s1[2]), "+f"(s1[3])
                    : "r"(aq[ms][c][0]), "r"(aq[ms][c][1]),
                      "r"(aq[ms][c][2]), "r"(aq[ms][c][3]),
                      "r"(kd[c][0]), "r"(kd[c][1]));
            }
            uint32_t wlo = mwv[2*ms], whi = mwv[2*ms+1];
            {
                float2 Plo = poshd[nid[2*ms]   - mid0 + 665];
                float2 Phi = poshd[nid[2*ms+1] - mid0 + 665];
                float p00 = (wlo & 1u) ? 0.f : __expf(s0[0]*scale + Plo.x);
                float p01 = (wlo & 2u) ? 0.f : __expf(s0[1]*scale + Plo.y);
                float p02 = (whi & 1u) ? 0.f : __expf(s0[2]*scale + Phi.x);
                float p03 = (whi & 2u) ? 0.f : __expf(s0[3]*scale + Phi.y);
                rsum[2*ms]   += p00 + p01;
                rsum[2*ms+1] += p02 + p03;
                pa[ms][0] = pack_h2(p00, p01);
                pa[ms][1] = pack_h2(p02, p03);
            }
            if (kt < KT16-1) {
                int mid1 = midv[m0 + 8];
                float2 Plo = poshd[nid[2*ms]   - mid1 + 665];
                float2 Phi = poshd[nid[2*ms+1] - mid1 + 665];
                float p10 = (wlo & 0x100u) ? 0.f : __expf(s1[0]*scale + Plo.x);
                float p11 = (wlo & 0x200u) ? 0.f : __expf(s1[1]*scale + Plo.y);
                float p12 = (whi & 0x100u) ? 0.f : __expf(s1[2]*scale + Phi.x);
                float p13 = (whi & 0x200u) ? 0.f : __expf(s1[3]*scale + Phi.y);
                rsum[2*ms]   += p10 + p11;
                rsum[2*ms+1] += p12 + p13;
                pa[ms][2] = pack_h2(p10, p11);
                pa[ms][3] = pack_h2(p12, p13);
            } else {
                pa[ms][2] = 0u; pa[ms][3] = 0u;
            }
        }

        // O += P V : V frags loaded once, used by both m16 tiles
        #pragma unroll
        for (int dt = 0; dt < 4; dt++) {
            uint32_t vb0 = *(const uint32_t*)&Vth[(dt*8 + grp)*VT_STRH + kt*16 + 2*tig];
            uint32_t vb1 = *(const uint32_t*)&Vth[(dt*8 + grp)*VT_STRH + kt*16 + 2*tig + 8];
            #pragma unroll
            for (int ms = 0; ms < 2; ms++) {
                asm volatile(
                    "mma.sync.aligned.m16n8k16.row.col.f32.f16.f16.f32 "
                    "{%0,%1,%2,%3}, {%4,%5,%6,%7}, {%8,%9}, {%0,%1,%2,%3};"
                    : "+f"(o[ms][dt][0]), "+f"(o[ms][dt][1]),
                      "+f"(o[ms][dt][2]), "+f"(o[ms][dt][3])
                    : "r"(pa[ms][0]), "r"(pa[ms][1]), "r"(pa[ms][2]), "r"(pa[ms][3]),
                      "r"(vb0), "r"(vb1));
            }
        }
    }

    // row-sum reduce across quad, normalize, store
    float inv_[4];
    #pragma unroll
    for (int i = 0; i < 4; i++) {
        float s = rsum[i];
        s += __shfl_xor_sync(0xffffffffu, s, 1);
        s += __shfl_xor_sync(0xffffffffu, s, 2);
        inv_[i] = 1.f / s;
    }

    #pragma unroll
    for (int ms = 0; ms < 2; ms++) {
        int rlo = r0 + 16*ms;        // always < 216
        int rhi = rlo + 8;           // ms=1,w=6 can exceed
        #pragma unroll
        for (int dt = 0; dt < 4; dt++) {
            int d = dt*8 + 2*tig;
            *(uint32_t*)&obh[(size_t)rlo*CH + d] =
                pack_h2(o[ms][dt][0]*inv_[2*ms], o[ms][dt][1]*inv_[2*ms]);
            if (rhi < NTOK)
                *(uint32_t*)&obh[(size_t)rhi*CH + d] =
                    pack_h2(o[ms][dt][2]*inv_[2*ms+1], o[ms][dt][3]*inv_[2*ms+1]);
        }
    }
}

// ---------------- launch ----------------
extern "C" void kernel_launch(void* const* d_in, const int* in_sizes, int n_in,
                              void* d_out, int out_size)
{
    const float* x     = (const float*)d_in[0];
    const float* y     = (const float*)d_in[1];
    const float* mask  = (const float*)d_in[2];
    const float* Wqkv  = (const float*)d_in[3];
    const float* bqkv  = (const float*)d_in[4];
    const float* Wproj = (const float*)d_in[5];
    const float* bproj = (const float*)d_in[6];
    const float* ppw   = (const float*)d_in[7];
    const float* ppb   = (const float*)d_in[8];
    const float* g1    = (const float*)d_in[9];
    const float* be1   = (const float*)d_in[10];
    const float* w1    = (const float*)d_in[11];
    const float* b1    = (const float*)d_in[12];
    const float* g2    = (const float*)d_in[13];
    const float* be2   = (const float*)d_in[14];
    const float* w2    = (const float*)d_in[15];
    const float* b2    = (const float*)d_in[16];
    const float* g3    = (const float*)d_in[17];
    const float* be3   = (const float*)d_in[18];
    const float* w3    = (const float*)d_in[19];
    const float* b3    = (const float*)d_in[20];
    float* out = (float*)d_out;

    __half *qp, *kvp, *attp, *whp;
    cudaGetSymbolAddress((void**)&qp,   g_qh);
    cudaGetSymbolAddress((void**)&kvp,  g_kvh);
    cudaGetSymbolAddress((void**)&attp, g_atth);
    cudaGetSymbolAddress((void**)&whp,  g_wh);

    pos_mlp_kernel<<<(M_POS+255)/256, 256>>>(ppw, ppb, g1, be1, w1, b1,
                                             g2, be2, w2, b2, g3, be3, w3, b3);
    conv_w_kernel<<<(4*CH*CH/4 + 255)/256, 256>>>(Wqkv, Wproj);
    mask_bits_kernel<<<(NG_*NTOK*32 + 255)/256, 256>>>(mask);

    cudaFuncSetAttribute(gemm_f16_big<false,true>,
                         cudaFuncAttributeMaxDynamicSharedMemorySize, GSMEM);
    cudaFuncSetAttribute(gemm_f16_big<true,false>,
                         cudaFuncAttributeMaxDynamicSharedMemorySize, GSMEM);

    // Q = x @ Wq^T + bq  -> half
    gemm_f16_big<false,true><<<MROWS/128, 256, GSMEM>>>(x, whp, bqkv, qp, CH);
    // KV = y @ Wkv^T + bkv -> half
    gemm_f16_big<false,true><<<MROWS/128, 256, GSMEM>>>(y, whp + (size_t)CH*CH,
                                                        bqkv + CH, kvp, 2*CH);
    // fused attention (m32 per warp; bitmask in SMEM)
    {
        size_t smem = (size_t)(NKP*KS_STRH + 32*VT_STRH)*2
                    + (size_t)M_POS*8 + (size_t)216*9*4 + (size_t)NTOK*2;
        cudaFuncSetAttribute(attn_tc_kernel, cudaFuncAttributeMaxDynamicSharedMemorySize, (int)smem);
        attn_tc_kernel<<<B_*HEADS, 224, smem>>>();
    }
    // out = att @ Wproj^T + bproj  (half A, float out)
    gemm_f16_big<true,false><<<MROWS/128, 256, GSMEM>>>(attp, whp + (size_t)3*CH*CH,
                                                        bproj, out, CH);
}